// round 1
// baseline (speedup 1.0000x reference)
#include <cuda_runtime.h>
#include <math.h>

// Problem constants
#define B 8
#define S 1024
#define D 1024
#define H 16
#define HD 64
#define MROWS (B * S)   // 8192

// ---------------- scratch (no runtime allocation allowed) ----------------
__device__ float g_q[MROWS * D];
__device__ float g_k[MROWS * D];
__device__ float g_v[MROWS * D];
__device__ float g_ao[MROWS * D];

// ---------------- GEMM: C[M,N] = A[M,K] * Bw[N,K]^T (nn.Linear) ----------
// Tiles: BM=64, BN=64, BK=16; 256 threads; 4x4 microtile per thread.
#define BM 64
#define BN 64
#define BK 16

__global__ void gemm_nt_kernel(const float* __restrict__ A,
                               const float* __restrict__ Bw,
                               float* __restrict__ C,
                               int M, int N, int K) {
    __shared__ float As[BK][BM + 1];
    __shared__ float Bs[BK][BN + 1];

    const int tid = threadIdx.x;          // 0..255
    const int tx = tid & 15;              // 0..15 (N dir)
    const int ty = tid >> 4;              // 0..15 (M dir)
    const int bn = blockIdx.x * BN;
    const int bm = blockIdx.y * BM;

    const float* Ab = A + (size_t)bm * K;
    const float* Bb = Bw + (size_t)bn * K;

    float acc[4][4];
#pragma unroll
    for (int i = 0; i < 4; i++)
#pragma unroll
        for (int j = 0; j < 4; j++) acc[i][j] = 0.0f;

    for (int k0 = 0; k0 < K; k0 += BK) {
        // load A tile [BM x BK] -> As[c][r]
#pragma unroll
        for (int i = tid; i < BM * BK; i += 256) {
            int r = i >> 4;          // /16
            int c = i & 15;
            As[c][r] = Ab[(size_t)r * K + k0 + c];
        }
#pragma unroll
        for (int i = tid; i < BN * BK; i += 256) {
            int r = i >> 4;
            int c = i & 15;
            Bs[c][r] = Bb[(size_t)r * K + k0 + c];
        }
        __syncthreads();

#pragma unroll
        for (int k = 0; k < BK; k++) {
            float a[4], b[4];
#pragma unroll
            for (int i = 0; i < 4; i++) a[i] = As[k][ty * 4 + i];
#pragma unroll
            for (int j = 0; j < 4; j++) b[j] = Bs[k][tx * 4 + j];
#pragma unroll
            for (int i = 0; i < 4; i++)
#pragma unroll
                for (int j = 0; j < 4; j++) acc[i][j] = fmaf(a[i], b[j], acc[i][j]);
        }
        __syncthreads();
    }

#pragma unroll
    for (int i = 0; i < 4; i++) {
        const int row = bm + ty * 4 + i;
#pragma unroll
        for (int j = 0; j < 4; j++) {
            C[(size_t)row * N + bn + tx * 4 + j] = acc[i][j];
        }
    }
}

// ---------------- Fused attention (flash-style, fp32) --------------------
// One block = one (b, h, 64-row q-tile). 256 threads, each owns a 4x4
// micro-tile of the 64x64 score block and 4x4 of the 64x64 output tile.
// smem: Qs[64][64] | Ks[64][65] (reused as P) | Vs[64][64]  = 49408 bytes.
__global__ void attn_kernel(const float* __restrict__ Q,
                            const float* __restrict__ K,
                            const float* __restrict__ V,
                            float* __restrict__ O) {
    extern __shared__ float sm[];
    float* Qs = sm;                 // 64*64
    float* Ks = sm + 64 * 64;       // 64*65  (also holds P)
    float* Vs = Ks + 64 * 65;       // 64*64

    const int tid = threadIdx.x;
    const int tx = tid & 15;
    const int ty = tid >> 4;
    const int b = blockIdx.z;
    const int h = blockIdx.y;
    const int q0 = blockIdx.x * 64;

    const float* Qbase = Q + ((size_t)(b * S + q0) * D) + h * HD;
    const float* Kbase = K + ((size_t)(b * S) * D) + h * HD;
    const float* Vbase = V + ((size_t)(b * S) * D) + h * HD;

    // load Q tile, fold in 1/sqrt(HD) = 0.125
#pragma unroll
    for (int i = tid; i < 64 * 64; i += 256) {
        int r = i >> 6, c = i & 63;
        Qs[r * 64 + c] = Qbase[(size_t)r * D + c] * 0.125f;
    }

    float m[4], l[4], o[4][4];
#pragma unroll
    for (int i = 0; i < 4; i++) {
        m[i] = -1e30f;
        l[i] = 0.0f;
#pragma unroll
        for (int j = 0; j < 4; j++) o[i][j] = 0.0f;
    }

    for (int kt = 0; kt < S; kt += 64) {
        __syncthreads();  // previous P/V reads done; Q visible on iter 0
#pragma unroll
        for (int i = tid; i < 64 * 64; i += 256) {
            int r = i >> 6, c = i & 63;
            Ks[r * 65 + c] = Kbase[(size_t)(kt + r) * D + c];
            Vs[r * 64 + c] = Vbase[(size_t)(kt + r) * D + c];
        }
        __syncthreads();

        // scores s = Q_tile . K_tile^T  (Q pre-scaled)
        float s[4][4];
#pragma unroll
        for (int i = 0; i < 4; i++)
#pragma unroll
            for (int j = 0; j < 4; j++) s[i][j] = 0.0f;

#pragma unroll 8
        for (int d = 0; d < 64; d++) {
            float qv[4], kv[4];
#pragma unroll
            for (int i = 0; i < 4; i++) qv[i] = Qs[(ty * 4 + i) * 64 + d];
#pragma unroll
            for (int j = 0; j < 4; j++) kv[j] = Ks[(tx * 4 + j) * 65 + d];
#pragma unroll
            for (int i = 0; i < 4; i++)
#pragma unroll
                for (int j = 0; j < 4; j++) s[i][j] = fmaf(qv[i], kv[j], s[i][j]);
        }

        // online softmax update (row stats across the 16 tx-threads)
#pragma unroll
        for (int i = 0; i < 4; i++) {
            float rm = fmaxf(fmaxf(s[i][0], s[i][1]), fmaxf(s[i][2], s[i][3]));
#pragma unroll
            for (int off = 8; off > 0; off >>= 1)
                rm = fmaxf(rm, __shfl_xor_sync(0xffffffffu, rm, off, 16));
            float mn = fmaxf(m[i], rm);
            float alpha = __expf(m[i] - mn);
            float rs = 0.0f;
#pragma unroll
            for (int j = 0; j < 4; j++) {
                s[i][j] = __expf(s[i][j] - mn);
                rs += s[i][j];
            }
#pragma unroll
            for (int off = 8; off > 0; off >>= 1)
                rs += __shfl_xor_sync(0xffffffffu, rs, off, 16);
            l[i] = l[i] * alpha + rs;
#pragma unroll
            for (int j = 0; j < 4; j++) o[i][j] *= alpha;
            m[i] = mn;
        }

        __syncthreads();  // everyone done reading Ks before overwrite with P
#pragma unroll
        for (int i = 0; i < 4; i++)
#pragma unroll
            for (int j = 0; j < 4; j++)
                Ks[(ty * 4 + i) * 65 + tx * 4 + j] = s[i][j];
        __syncthreads();

        // O += P @ V
#pragma unroll 8
        for (int k = 0; k < 64; k++) {
            float pv[4], vv[4];
#pragma unroll
            for (int i = 0; i < 4; i++) pv[i] = Ks[(ty * 4 + i) * 65 + k];
#pragma unroll
            for (int j = 0; j < 4; j++) vv[j] = Vs[k * 64 + tx * 4 + j];
#pragma unroll
            for (int i = 0; i < 4; i++)
#pragma unroll
                for (int j = 0; j < 4; j++) o[i][j] = fmaf(pv[i], vv[j], o[i][j]);
        }
    }

    float* Obase = O + ((size_t)(b * S + q0) * D) + h * HD;
#pragma unroll
    for (int i = 0; i < 4; i++) {
        float inv_l = 1.0f / l[i];
#pragma unroll
        for (int j = 0; j < 4; j++)
            Obase[(size_t)(ty * 4 + i) * D + tx * 4 + j] = o[i][j] * inv_l;
    }
}

// ---------------- launch ----------------
extern "C" void kernel_launch(void* const* d_in, const int* in_sizes, int n_in,
                              void* d_out, int out_size) {
    const float* x  = (const float*)d_in[0];
    const float* wq = (const float*)d_in[1];
    const float* wk = (const float*)d_in[2];
    const float* wv = (const float*)d_in[3];
    const float* wo = (const float*)d_in[4];
    float* out = (float*)d_out;

    float* q;  cudaGetSymbolAddress((void**)&q,  g_q);
    float* k;  cudaGetSymbolAddress((void**)&k,  g_k);
    float* v;  cudaGetSymbolAddress((void**)&v,  g_v);
    float* ao; cudaGetSymbolAddress((void**)&ao, g_ao);

    const int smem_attn = (64 * 64 + 64 * 65 + 64 * 64) * sizeof(float);  // 49408
    cudaFuncSetAttribute(attn_kernel, cudaFuncAttributeMaxDynamicSharedMemorySize,
                         smem_attn);

    dim3 gemm_grid(D / BN, MROWS / BM);   // (16, 128)
    gemm_nt_kernel<<<gemm_grid, 256>>>(x, wq, q, MROWS, D, D);
    gemm_nt_kernel<<<gemm_grid, 256>>>(x, wk, k, MROWS, D, D);
    gemm_nt_kernel<<<gemm_grid, 256>>>(x, wv, v, MROWS, D, D);

    dim3 attn_grid(S / 64, H, B);         // (16, 16, 8)
    attn_kernel<<<attn_grid, 256, smem_attn>>>(q, k, v, ao);

    gemm_nt_kernel<<<gemm_grid, 256>>>(ao, wo, out, MROWS, D, D);
}

// round 3
// speedup vs baseline: 2.2143x; 2.2143x over previous
#include <cuda_runtime.h>
#include <math.h>
#include <stdint.h>

// Problem constants
#define B 8
#define S 1024
#define D 1024
#define H 16
#define HD 64
#define MROWS (B * S)   // 8192

// ---------------- scratch (no runtime allocation allowed) ----------------
__device__ float g_q[MROWS * D];
__device__ float g_k[MROWS * D];
__device__ float g_v[MROWS * D];
__device__ float g_ao[MROWS * D];

// ===================== tf32 mma.sync GEMM: C = A * W^T ====================
// C[M,1024] = A[M,1024] x W[1024,1024]^T  (nn.Linear). CTA tile 128x128,
// K-tile 32, 8 warps (256 thr), warp tile 32x64 via m16n8k8 tf32 HMMA.
// Fragments are pre-permuted into smem so the mainloop is LDS.128/64 + MMA.

__device__ __forceinline__ uint32_t f2tf32(float v) {
    uint32_t u;
    asm("cvt.rna.tf32.f32 %0, %1;" : "=r"(u) : "f"(v));
    return u;
}

__device__ __forceinline__ void mma_tf32(float* c, const uint32_t* a,
                                         const uint32_t* b) {
    asm volatile(
        "mma.sync.aligned.m16n8k8.row.col.f32.tf32.tf32.f32 "
        "{%0,%1,%2,%3}, {%4,%5,%6,%7}, {%8,%9}, {%0,%1,%2,%3};"
        : "+f"(c[0]), "+f"(c[1]), "+f"(c[2]), "+f"(c[3])
        : "r"(a[0]), "r"(a[1]), "r"(a[2]), "r"(a[3]), "r"(b[0]), "r"(b[1]));
}

// smem per buffer: A_perm 4096 floats + B_perm 4096 floats. 2 buffers.
#define GEMM_SMEM (2 * (4096 + 4096) * 4)

__global__ void __launch_bounds__(256, 1)
gemm_tc_kernel(const float* __restrict__ A, const float* __restrict__ W,
               float* __restrict__ C) {
    extern __shared__ float sm[];
    // layout: [buf][A(4096) | B(4096)]
    const int tid = threadIdx.x;
    const int lane = tid & 31;
    const int wid = tid >> 5;
    const int wm = wid & 3;           // 4 warps along M (32 rows each)
    const int wn = wid >> 2;          // 2 warps along N (64 cols each)
    const int bn = blockIdx.x * 128;
    const int bm = blockIdx.y * 128;

    float acc[2][8][4];
#pragma unroll
    for (int m = 0; m < 2; m++)
#pragma unroll
        for (int n = 0; n < 8; n++)
#pragma unroll
            for (int i = 0; i < 4; i++) acc[m][n][i] = 0.0f;

    // global load: each thread 4 x float4 from A and W tiles (coalesced)
    const int gr = tid >> 3;          // base row   (0..31, step 32 per it)
    const int gc = (tid & 7) * 4;     // col within 32

    float4 ra[4], rb[4];
    auto ldg = [&](int k0) {
#pragma unroll
        for (int it = 0; it < 4; it++) {
            int r = it * 32 + gr;
            ra[it] = *reinterpret_cast<const float4*>(
                A + (size_t)(bm + r) * 1024 + k0 + gc);
            rb[it] = *reinterpret_cast<const float4*>(
                W + (size_t)(bn + r) * 1024 + k0 + gc);
        }
    };

    // permuted stores: element (r, c) of the 128x32 tile -> fragment layout
    auto sts = [&](float* sA, float* sB) {
#pragma unroll
        for (int it = 0; it < 4; it++) {
            int r = it * 32 + gr;
            const float va[4] = {ra[it].x, ra[it].y, ra[it].z, ra[it].w};
            const float vb[4] = {rb[it].x, rb[it].y, rb[it].z, rb[it].w};
#pragma unroll
            for (int j = 0; j < 4; j++) {
                int c = gc + j;
                // A frag (m16k8): lane=(r%8)*4+(c%4), reg=(r/8%2)+2*((c%8)/4)
                {
                    int mtile = r >> 4, rr = r & 15;
                    int kstep = c >> 3, cc = c & 7;
                    int ln = (rr & 7) * 4 + (cc & 3);
                    int rg = (rr >> 3) + 2 * (cc >> 2);
                    sA[((mtile * 4 + kstep) * 32 + ln) * 4 + rg] =
                        __uint_as_float(f2tf32(va[j]));
                }
                // B frag (k8n8 col-major): lane=(n%8)*4+(k%4), reg=(k%8)/4
                {
                    int ntile = r >> 3, nn = r & 7;     // r is the N index
                    int kstep = c >> 3, kk = c & 7;
                    int ln = nn * 4 + (kk & 3);
                    int rg = kk >> 2;
                    sB[((ntile * 4 + kstep) * 32 + ln) * 2 + rg] =
                        __uint_as_float(f2tf32(vb[j]));
                }
            }
        }
    };

    auto compute = [&](const float* sA, const float* sB) {
#pragma unroll
        for (int ks = 0; ks < 4; ks++) {
            uint32_t af[2][4];
            uint32_t bf[8][2];
#pragma unroll
            for (int m = 0; m < 2; m++) {
                const float4 v = *reinterpret_cast<const float4*>(
                    sA + (((wm * 2 + m) * 4 + ks) * 32 + lane) * 4);
                af[m][0] = __float_as_uint(v.x);
                af[m][1] = __float_as_uint(v.y);
                af[m][2] = __float_as_uint(v.z);
                af[m][3] = __float_as_uint(v.w);
            }
#pragma unroll
            for (int n = 0; n < 8; n++) {
                const float2 v = *reinterpret_cast<const float2*>(
                    sB + (((wn * 8 + n) * 4 + ks) * 32 + lane) * 2);
                bf[n][0] = __float_as_uint(v.x);
                bf[n][1] = __float_as_uint(v.y);
            }
#pragma unroll
            for (int m = 0; m < 2; m++)
#pragma unroll
                for (int n = 0; n < 8; n++) mma_tf32(acc[m][n], af[m], bf[n]);
        }
    };

    float* buf0 = sm;
    float* buf1 = sm + 8192;

    ldg(0);
    sts(buf0, buf0 + 4096);
    __syncthreads();

    for (int t = 0; t < 32; t++) {
        float* cur = (t & 1) ? buf1 : buf0;
        float* nxt = (t & 1) ? buf0 : buf1;
        if (t < 31) ldg((t + 1) * 32);
        compute(cur, cur + 4096);
        if (t < 31) {
            sts(nxt, nxt + 4096);
            __syncthreads();
        }
    }

    // epilogue: C frag m16n8: c0=C[t/4][(t%4)*2], c2/c3 at row+8
    const int qr = lane >> 2;         // 0..7
    const int qc = (lane & 3) * 2;    // 0,2,4,6
#pragma unroll
    for (int m = 0; m < 2; m++) {
        const int row0 = bm + wm * 32 + m * 16 + qr;
#pragma unroll
        for (int n = 0; n < 8; n++) {
            const int col = bn + wn * 64 + n * 8 + qc;
            *reinterpret_cast<float2*>(C + (size_t)row0 * 1024 + col) =
                make_float2(acc[m][n][0], acc[m][n][1]);
            *reinterpret_cast<float2*>(C + (size_t)(row0 + 8) * 1024 + col) =
                make_float2(acc[m][n][2], acc[m][n][3]);
        }
    }
}

// ---------------- Fused attention (flash-style, fp32) — unchanged --------
__global__ void attn_kernel(const float* __restrict__ Q,
                            const float* __restrict__ K,
                            const float* __restrict__ V,
                            float* __restrict__ O) {
    extern __shared__ float sm[];
    float* Qs = sm;                 // 64*64
    float* Ks = sm + 64 * 64;       // 64*65  (also holds P)
    float* Vs = Ks + 64 * 65;       // 64*64

    const int tid = threadIdx.x;
    const int tx = tid & 15;
    const int ty = tid >> 4;
    const int b = blockIdx.z;
    const int h = blockIdx.y;
    const int q0 = blockIdx.x * 64;

    const float* Qbase = Q + ((size_t)(b * S + q0) * D) + h * HD;
    const float* Kbase = K + ((size_t)(b * S) * D) + h * HD;
    const float* Vbase = V + ((size_t)(b * S) * D) + h * HD;

#pragma unroll
    for (int i = tid; i < 64 * 64; i += 256) {
        int r = i >> 6, c = i & 63;
        Qs[r * 64 + c] = Qbase[(size_t)r * D + c] * 0.125f;
    }

    float m[4], l[4], o[4][4];
#pragma unroll
    for (int i = 0; i < 4; i++) {
        m[i] = -1e30f;
        l[i] = 0.0f;
#pragma unroll
        for (int j = 0; j < 4; j++) o[i][j] = 0.0f;
    }

    for (int kt = 0; kt < S; kt += 64) {
        __syncthreads();
#pragma unroll
        for (int i = tid; i < 64 * 64; i += 256) {
            int r = i >> 6, c = i & 63;
            Ks[r * 65 + c] = Kbase[(size_t)(kt + r) * D + c];
            Vs[r * 64 + c] = Vbase[(size_t)(kt + r) * D + c];
        }
        __syncthreads();

        float s[4][4];
#pragma unroll
        for (int i = 0; i < 4; i++)
#pragma unroll
            for (int j = 0; j < 4; j++) s[i][j] = 0.0f;

#pragma unroll 8
        for (int d = 0; d < 64; d++) {
            float qv[4], kv[4];
#pragma unroll
            for (int i = 0; i < 4; i++) qv[i] = Qs[(ty * 4 + i) * 64 + d];
#pragma unroll
            for (int j = 0; j < 4; j++) kv[j] = Ks[(tx * 4 + j) * 65 + d];
#pragma unroll
            for (int i = 0; i < 4; i++)
#pragma unroll
                for (int j = 0; j < 4; j++) s[i][j] = fmaf(qv[i], kv[j], s[i][j]);
        }

#pragma unroll
        for (int i = 0; i < 4; i++) {
            float rm = fmaxf(fmaxf(s[i][0], s[i][1]), fmaxf(s[i][2], s[i][3]));
#pragma unroll
            for (int off = 8; off > 0; off >>= 1)
                rm = fmaxf(rm, __shfl_xor_sync(0xffffffffu, rm, off, 16));
            float mn = fmaxf(m[i], rm);
            float alpha = __expf(m[i] - mn);
            float rs = 0.0f;
#pragma unroll
            for (int j = 0; j < 4; j++) {
                s[i][j] = __expf(s[i][j] - mn);
                rs += s[i][j];
            }
#pragma unroll
            for (int off = 8; off > 0; off >>= 1)
                rs += __shfl_xor_sync(0xffffffffu, rs, off, 16);
            l[i] = l[i] * alpha + rs;
#pragma unroll
            for (int j = 0; j < 4; j++) o[i][j] *= alpha;
            m[i] = mn;
        }

        __syncthreads();
#pragma unroll
        for (int i = 0; i < 4; i++)
#pragma unroll
            for (int j = 0; j < 4; j++)
                Ks[(ty * 4 + i) * 65 + tx * 4 + j] = s[i][j];
        __syncthreads();

#pragma unroll 8
        for (int k = 0; k < 64; k++) {
            float pv[4], vv[4];
#pragma unroll
            for (int i = 0; i < 4; i++) pv[i] = Ks[(ty * 4 + i) * 65 + k];
#pragma unroll
            for (int j = 0; j < 4; j++) vv[j] = Vs[k * 64 + tx * 4 + j];
#pragma unroll
            for (int i = 0; i < 4; i++)
#pragma unroll
                for (int j = 0; j < 4; j++) o[i][j] = fmaf(pv[i], vv[j], o[i][j]);
        }
    }

    float* Obase = O + ((size_t)(b * S + q0) * D) + h * HD;
#pragma unroll
    for (int i = 0; i < 4; i++) {
        float inv_l = 1.0f / l[i];
#pragma unroll
        for (int j = 0; j < 4; j++)
            Obase[(size_t)(ty * 4 + i) * D + tx * 4 + j] = o[i][j] * inv_l;
    }
}

// ---------------- launch ----------------
extern "C" void kernel_launch(void* const* d_in, const int* in_sizes, int n_in,
                              void* d_out, int out_size) {
    const float* x  = (const float*)d_in[0];
    const float* wq = (const float*)d_in[1];
    const float* wk = (const float*)d_in[2];
    const float* wv = (const float*)d_in[3];
    const float* wo = (const float*)d_in[4];
    float* out = (float*)d_out;

    float* q;  cudaGetSymbolAddress((void**)&q,  g_q);
    float* k;  cudaGetSymbolAddress((void**)&k,  g_k);
    float* v;  cudaGetSymbolAddress((void**)&v,  g_v);
    float* ao; cudaGetSymbolAddress((void**)&ao, g_ao);

    cudaFuncSetAttribute(gemm_tc_kernel,
                         cudaFuncAttributeMaxDynamicSharedMemorySize, GEMM_SMEM);
    const int smem_attn = (64 * 64 + 64 * 65 + 64 * 64) * sizeof(float);  // 49408
    cudaFuncSetAttribute(attn_kernel, cudaFuncAttributeMaxDynamicSharedMemorySize,
                         smem_attn);

    dim3 gemm_grid(D / 128, MROWS / 128);   // (8, 64)
    gemm_tc_kernel<<<gemm_grid, 256, GEMM_SMEM>>>(x, wq, q);
    gemm_tc_kernel<<<gemm_grid, 256, GEMM_SMEM>>>(x, wk, k);
    gemm_tc_kernel<<<gemm_grid, 256, GEMM_SMEM>>>(x, wv, v);

    dim3 attn_grid(S / 64, H, B);           // (16, 16, 8)
    attn_kernel<<<attn_grid, 256, smem_attn>>>(q, k, v, ao);

    gemm_tc_kernel<<<gemm_grid, 256, GEMM_SMEM>>>(ao, wo, out);
}

// round 4
// speedup vs baseline: 3.4301x; 1.5490x over previous
#include <cuda_runtime.h>
#include <math.h>
#include <stdint.h>

// Problem constants
#define B 8
#define S 1024
#define D 1024
#define H 16
#define HD 64
#define MROWS (B * S)   // 8192

// ---------------- scratch (no runtime allocation allowed) ----------------
__device__ float g_q[MROWS * D];
__device__ float g_k[MROWS * D];
__device__ float g_v[MROWS * D];
__device__ float g_ao[MROWS * D];

// ===================== shared tf32 mma helpers ============================
__device__ __forceinline__ uint32_t f2tf32(float v) {
    uint32_t u;
    asm("cvt.rna.tf32.f32 %0, %1;" : "=r"(u) : "f"(v));
    return u;
}

__device__ __forceinline__ void mma_tf32(float* c, const uint32_t* a,
                                         const uint32_t* b) {
    asm volatile(
        "mma.sync.aligned.m16n8k8.row.col.f32.tf32.tf32.f32 "
        "{%0,%1,%2,%3}, {%4,%5,%6,%7}, {%8,%9}, {%0,%1,%2,%3};"
        : "+f"(c[0]), "+f"(c[1]), "+f"(c[2]), "+f"(c[3])
        : "r"(a[0]), "r"(a[1]), "r"(a[2]), "r"(a[3]), "r"(b[0]), "r"(b[1]));
}

// ===================== tf32 mma.sync GEMM: C = A * W^T ====================
#define GEMM_SMEM (2 * (4096 + 4096) * 4)

__global__ void __launch_bounds__(256, 1)
gemm_tc_kernel(const float* __restrict__ A, const float* __restrict__ W,
               float* __restrict__ C) {
    extern __shared__ float sm[];
    const int tid = threadIdx.x;
    const int lane = tid & 31;
    const int wid = tid >> 5;
    const int wm = wid & 3;
    const int wn = wid >> 2;
    const int bn = blockIdx.x * 128;
    const int bm = blockIdx.y * 128;

    float acc[2][8][4];
#pragma unroll
    for (int m = 0; m < 2; m++)
#pragma unroll
        for (int n = 0; n < 8; n++)
#pragma unroll
            for (int i = 0; i < 4; i++) acc[m][n][i] = 0.0f;

    const int gr = tid >> 3;
    const int gc = (tid & 7) * 4;

    float4 ra[4], rb[4];
    auto ldg = [&](int k0) {
#pragma unroll
        for (int it = 0; it < 4; it++) {
            int r = it * 32 + gr;
            ra[it] = *reinterpret_cast<const float4*>(
                A + (size_t)(bm + r) * 1024 + k0 + gc);
            rb[it] = *reinterpret_cast<const float4*>(
                W + (size_t)(bn + r) * 1024 + k0 + gc);
        }
    };

    auto sts = [&](float* sA, float* sB) {
#pragma unroll
        for (int it = 0; it < 4; it++) {
            int r = it * 32 + gr;
            const float va[4] = {ra[it].x, ra[it].y, ra[it].z, ra[it].w};
            const float vb[4] = {rb[it].x, rb[it].y, rb[it].z, rb[it].w};
#pragma unroll
            for (int j = 0; j < 4; j++) {
                int c = gc + j;
                {
                    int mtile = r >> 4, rr = r & 15;
                    int kstep = c >> 3, cc = c & 7;
                    int ln = (rr & 7) * 4 + (cc & 3);
                    int rg = (rr >> 3) + 2 * (cc >> 2);
                    sA[((mtile * 4 + kstep) * 32 + ln) * 4 + rg] =
                        __uint_as_float(f2tf32(va[j]));
                }
                {
                    int ntile = r >> 3, nn = r & 7;
                    int kstep = c >> 3, kk = c & 7;
                    int ln = nn * 4 + (kk & 3);
                    int rg = kk >> 2;
                    sB[((ntile * 4 + kstep) * 32 + ln) * 2 + rg] =
                        __uint_as_float(f2tf32(vb[j]));
                }
            }
        }
    };

    auto compute = [&](const float* sA, const float* sB) {
#pragma unroll
        for (int ks = 0; ks < 4; ks++) {
            uint32_t af[2][4];
            uint32_t bf[8][2];
#pragma unroll
            for (int m = 0; m < 2; m++) {
                const float4 v = *reinterpret_cast<const float4*>(
                    sA + (((wm * 2 + m) * 4 + ks) * 32 + lane) * 4);
                af[m][0] = __float_as_uint(v.x);
                af[m][1] = __float_as_uint(v.y);
                af[m][2] = __float_as_uint(v.z);
                af[m][3] = __float_as_uint(v.w);
            }
#pragma unroll
            for (int n = 0; n < 8; n++) {
                const float2 v = *reinterpret_cast<const float2*>(
                    sB + (((wn * 8 + n) * 4 + ks) * 32 + lane) * 2);
                bf[n][0] = __float_as_uint(v.x);
                bf[n][1] = __float_as_uint(v.y);
            }
#pragma unroll
            for (int m = 0; m < 2; m++)
#pragma unroll
                for (int n = 0; n < 8; n++) mma_tf32(acc[m][n], af[m], bf[n]);
        }
    };

    float* buf0 = sm;
    float* buf1 = sm + 8192;

    ldg(0);
    sts(buf0, buf0 + 4096);
    __syncthreads();

    for (int t = 0; t < 32; t++) {
        float* cur = (t & 1) ? buf1 : buf0;
        float* nxt = (t & 1) ? buf0 : buf1;
        if (t < 31) ldg((t + 1) * 32);
        compute(cur, cur + 4096);
        if (t < 31) {
            sts(nxt, nxt + 4096);
            __syncthreads();
        }
    }

    const int qr = lane >> 2;
    const int qc = (lane & 3) * 2;
#pragma unroll
    for (int m = 0; m < 2; m++) {
        const int row0 = bm + wm * 32 + m * 16 + qr;
#pragma unroll
        for (int n = 0; n < 8; n++) {
            const int col = bn + wn * 64 + n * 8 + qc;
            *reinterpret_cast<float2*>(C + (size_t)row0 * 1024 + col) =
                make_float2(acc[m][n][0], acc[m][n][1]);
            *reinterpret_cast<float2*>(C + (size_t)(row0 + 8) * 1024 + col) =
                make_float2(acc[m][n][2], acc[m][n][3]);
        }
    }
}

// ============ tf32 tensor-core flash attention ============================
// CTA: 256 thr (8 warps), 128 q-rows; warp owns 16 rows (m16).
// KV tile = 64 keys. K,V in smem as [row=key][col=d], pitch 68 floats,
// values pre-converted to tf32 bits. B-frag reads are conflict-free for
// both QK^T (n=key,k=d) and PV (n=d,k=key) without any transpose.
#define KVPITCH 68
#define ATTN_SMEM (2 * 64 * KVPITCH * 4)   // 34816 B

__global__ void __launch_bounds__(256, 1)
attn_tc_kernel(const float* __restrict__ Q, const float* __restrict__ K,
               const float* __restrict__ V, float* __restrict__ O) {
    extern __shared__ float sm[];
    float* Ks = sm;                  // 64 x 68
    float* Vs = sm + 64 * KVPITCH;   // 64 x 68

    const int tid = threadIdx.x;
    const int lane = tid & 31;
    const int wid = tid >> 5;
    const int c = lane & 3;
    const int r = lane >> 2;
    const int b = blockIdx.z;
    const int h = blockIdx.y;
    const int q0 = blockIdx.x * 128;
    const int wrow = wid * 16;

    const float* Qb = Q + ((size_t)(b * S + q0) * D) + h * HD;
    const float* Kb = K + ((size_t)b * S) * D + h * HD;
    const float* Vb = V + ((size_t)b * S) * D + h * HD;

    // Q fragments: qf[ks] = A-frag of Q[wrow..wrow+15][ks*8..ks*8+7] * 0.125
    uint32_t qf[8][4];
#pragma unroll
    for (int ks = 0; ks < 8; ks++) {
        const int row0 = wrow + r, row1 = row0 + 8, col = ks * 8 + c;
        qf[ks][0] = f2tf32(Qb[(size_t)row0 * D + col] * 0.125f);
        qf[ks][1] = f2tf32(Qb[(size_t)row1 * D + col] * 0.125f);
        qf[ks][2] = f2tf32(Qb[(size_t)row0 * D + col + 4] * 0.125f);
        qf[ks][3] = f2tf32(Qb[(size_t)row1 * D + col + 4] * 0.125f);
    }

    float oacc[8][4];
#pragma unroll
    for (int n = 0; n < 8; n++)
#pragma unroll
        for (int i = 0; i < 4; i++) oacc[n][i] = 0.0f;
    float m0 = -1e30f, m1 = -1e30f, l0 = 0.0f, l1 = 0.0f;

    for (int kt0 = 0; kt0 < S; kt0 += 64) {
        __syncthreads();
        // load K,V tiles (tf32-converted on store)
#pragma unroll
        for (int i = 0; i < 4; i++) {
            const int idx = tid + i * 256;
            const int row = idx >> 4, c4 = (idx & 15) * 4;
            float4 kv = *reinterpret_cast<const float4*>(
                Kb + (size_t)(kt0 + row) * D + c4);
            float4 vv = *reinterpret_cast<const float4*>(
                Vb + (size_t)(kt0 + row) * D + c4);
            float4 kc = make_float4(__uint_as_float(f2tf32(kv.x)),
                                    __uint_as_float(f2tf32(kv.y)),
                                    __uint_as_float(f2tf32(kv.z)),
                                    __uint_as_float(f2tf32(kv.w)));
            float4 vc = make_float4(__uint_as_float(f2tf32(vv.x)),
                                    __uint_as_float(f2tf32(vv.y)),
                                    __uint_as_float(f2tf32(vv.z)),
                                    __uint_as_float(f2tf32(vv.w)));
            *reinterpret_cast<float4*>(Ks + row * KVPITCH + c4) = kc;
            *reinterpret_cast<float4*>(Vs + row * KVPITCH + c4) = vc;
        }
        __syncthreads();

        // S = Q . K^T   (ks outer so the 8 accumulators pipeline)
        float sacc[8][4];
#pragma unroll
        for (int n = 0; n < 8; n++)
#pragma unroll
            for (int i = 0; i < 4; i++) sacc[n][i] = 0.0f;

#pragma unroll
        for (int ks = 0; ks < 8; ks++) {
#pragma unroll
            for (int nt = 0; nt < 8; nt++) {
                uint32_t bf[2];
                const float* kp = Ks + (nt * 8 + r) * KVPITCH + ks * 8 + c;
                bf[0] = __float_as_uint(kp[0]);
                bf[1] = __float_as_uint(kp[4]);
                mma_tf32(sacc[nt], qf[ks], bf);
            }
        }

        // online softmax on C-fragments (rows gr and gr+8)
        float rmax0 = -1e30f, rmax1 = -1e30f;
#pragma unroll
        for (int nt = 0; nt < 8; nt++) {
            rmax0 = fmaxf(rmax0, fmaxf(sacc[nt][0], sacc[nt][1]));
            rmax1 = fmaxf(rmax1, fmaxf(sacc[nt][2], sacc[nt][3]));
        }
#pragma unroll
        for (int off = 1; off <= 2; off <<= 1) {
            rmax0 = fmaxf(rmax0, __shfl_xor_sync(0xffffffffu, rmax0, off));
            rmax1 = fmaxf(rmax1, __shfl_xor_sync(0xffffffffu, rmax1, off));
        }
        const float mn0 = fmaxf(m0, rmax0);
        const float mn1 = fmaxf(m1, rmax1);
        const float alpha0 = __expf(m0 - mn0);
        const float alpha1 = __expf(m1 - mn1);
        float rs0 = 0.0f, rs1 = 0.0f;
#pragma unroll
        for (int nt = 0; nt < 8; nt++) {
            sacc[nt][0] = __expf(sacc[nt][0] - mn0);
            sacc[nt][1] = __expf(sacc[nt][1] - mn0);
            sacc[nt][2] = __expf(sacc[nt][2] - mn1);
            sacc[nt][3] = __expf(sacc[nt][3] - mn1);
            rs0 += sacc[nt][0] + sacc[nt][1];
            rs1 += sacc[nt][2] + sacc[nt][3];
        }
#pragma unroll
        for (int off = 1; off <= 2; off <<= 1) {
            rs0 += __shfl_xor_sync(0xffffffffu, rs0, off);
            rs1 += __shfl_xor_sync(0xffffffffu, rs1, off);
        }
        l0 = l0 * alpha0 + rs0;
        l1 = l1 * alpha1 + rs1;
        m0 = mn0;
        m1 = mn1;
#pragma unroll
        for (int nt = 0; nt < 8; nt++) {
            oacc[nt][0] *= alpha0;
            oacc[nt][1] *= alpha0;
            oacc[nt][2] *= alpha1;
            oacc[nt][3] *= alpha1;
        }

        // P (C-frag) -> A-frag via intra-quad shuffles, then O += P.V
        const int srcA = (lane & ~3) | (c >> 1);
        const int srcB = srcA + 2;
#pragma unroll
        for (int kt = 0; kt < 8; kt++) {
            const float v00 = __shfl_sync(0xffffffffu, sacc[kt][0], srcA);
            const float v01 = __shfl_sync(0xffffffffu, sacc[kt][1], srcA);
            const float v20 = __shfl_sync(0xffffffffu, sacc[kt][2], srcA);
            const float v21 = __shfl_sync(0xffffffffu, sacc[kt][3], srcA);
            const float w00 = __shfl_sync(0xffffffffu, sacc[kt][0], srcB);
            const float w01 = __shfl_sync(0xffffffffu, sacc[kt][1], srcB);
            const float w20 = __shfl_sync(0xffffffffu, sacc[kt][2], srcB);
            const float w21 = __shfl_sync(0xffffffffu, sacc[kt][3], srcB);
            uint32_t af[4];
            af[0] = f2tf32((c & 1) ? v01 : v00);
            af[1] = f2tf32((c & 1) ? v21 : v20);
            af[2] = f2tf32((c & 1) ? w01 : w00);
            af[3] = f2tf32((c & 1) ? w21 : w20);
#pragma unroll
            for (int nt = 0; nt < 8; nt++) {
                uint32_t bf[2];
                const float* vp = Vs + (kt * 8 + c) * KVPITCH + nt * 8 + r;
                bf[0] = __float_as_uint(vp[0]);
                bf[1] = __float_as_uint(vp[4 * KVPITCH]);
                mma_tf32(oacc[nt], af, bf);
            }
        }
    }

    // epilogue: divide by l, write out
    const float inv0 = 1.0f / l0;
    const float inv1 = 1.0f / l1;
    float* Ob = O + ((size_t)(b * S + q0 + wrow) * D) + h * HD;
#pragma unroll
    for (int nt = 0; nt < 8; nt++) {
        const int col = nt * 8 + 2 * c;
        *reinterpret_cast<float2*>(Ob + (size_t)r * D + col) =
            make_float2(oacc[nt][0] * inv0, oacc[nt][1] * inv0);
        *reinterpret_cast<float2*>(Ob + (size_t)(r + 8) * D + col) =
            make_float2(oacc[nt][2] * inv1, oacc[nt][3] * inv1);
    }
}

// ---------------- launch ----------------
extern "C" void kernel_launch(void* const* d_in, const int* in_sizes, int n_in,
                              void* d_out, int out_size) {
    const float* x  = (const float*)d_in[0];
    const float* wq = (const float*)d_in[1];
    const float* wk = (const float*)d_in[2];
    const float* wv = (const float*)d_in[3];
    const float* wo = (const float*)d_in[4];
    float* out = (float*)d_out;

    float* q;  cudaGetSymbolAddress((void**)&q,  g_q);
    float* k;  cudaGetSymbolAddress((void**)&k,  g_k);
    float* v;  cudaGetSymbolAddress((void**)&v,  g_v);
    float* ao; cudaGetSymbolAddress((void**)&ao, g_ao);

    cudaFuncSetAttribute(gemm_tc_kernel,
                         cudaFuncAttributeMaxDynamicSharedMemorySize, GEMM_SMEM);
    cudaFuncSetAttribute(attn_tc_kernel,
                         cudaFuncAttributeMaxDynamicSharedMemorySize, ATTN_SMEM);

    dim3 gemm_grid(D / 128, MROWS / 128);   // (8, 64)
    gemm_tc_kernel<<<gemm_grid, 256, GEMM_SMEM>>>(x, wq, q);
    gemm_tc_kernel<<<gemm_grid, 256, GEMM_SMEM>>>(x, wk, k);
    gemm_tc_kernel<<<gemm_grid, 256, GEMM_SMEM>>>(x, wv, v);

    dim3 attn_grid(S / 128, H, B);          // (8, 16, 8)
    attn_tc_kernel<<<attn_grid, 256, ATTN_SMEM>>>(q, k, v, ao);

    gemm_tc_kernel<<<gemm_grid, 256, GEMM_SMEM>>>(ao, wo, out);
}

// round 5
// speedup vs baseline: 4.6487x; 1.3553x over previous
#include <cuda_runtime.h>
#include <math.h>
#include <stdint.h>

// Problem constants
#define B 8
#define S 1024
#define D 1024
#define H 16
#define HD 64
#define MROWS (B * S)   // 8192

// ---------------- scratch (no runtime allocation allowed) ----------------
__device__ float g_q[MROWS * D];
__device__ float g_k[MROWS * D];
__device__ float g_v[MROWS * D];
__device__ float g_ao[MROWS * D];

// ===================== shared tf32 mma helpers ============================
__device__ __forceinline__ uint32_t f2tf32(float v) {
    uint32_t u;
    asm("cvt.rna.tf32.f32 %0, %1;" : "=r"(u) : "f"(v));
    return u;
}

__device__ __forceinline__ void mma_tf32(float* c, const uint32_t* a,
                                         const uint32_t* b) {
    asm volatile(
        "mma.sync.aligned.m16n8k8.row.col.f32.tf32.tf32.f32 "
        "{%0,%1,%2,%3}, {%4,%5,%6,%7}, {%8,%9}, {%0,%1,%2,%3};"
        : "+f"(c[0]), "+f"(c[1]), "+f"(c[2]), "+f"(c[3])
        : "r"(a[0]), "r"(a[1]), "r"(a[2]), "r"(a[3]), "r"(b[0]), "r"(b[1]));
}

// ===================== tf32 mma.sync GEMM: C = A * W^T ====================
// CTA tile 128x128, K-tile 32, 8 warps, warp tile 32x64 (m16n8k8).
// Tiles staged in NATURAL row-major layout, pitch 36 floats (36 mod 32 = 4
// -> fragment scalar LDS hit bank 4r+c: conflict-free). tf32 cvt at store.
#define GP 36
#define GSTAGE (128 * GP)            // floats per matrix per stage (4608)
#define GEMM_SMEM (2 * 2 * GSTAGE * 4)   // 73728 B

__global__ void __launch_bounds__(256, 2)
gemm_tc_kernel(const float* __restrict__ A, const float* __restrict__ W,
               float* __restrict__ C) {
    extern __shared__ float sm[];
    const int tid = threadIdx.x;
    const int lane = tid & 31;
    const int wid = tid >> 5;
    const int wm = wid & 3;           // 4 warps along M (32 rows)
    const int wn = wid >> 2;          // 2 warps along N (64 cols)
    const int c = lane & 3;
    const int r = lane >> 2;
    const int bn = blockIdx.x * 128;
    const int bm = blockIdx.y * 128;

    float acc[2][8][4];
#pragma unroll
    for (int m = 0; m < 2; m++)
#pragma unroll
        for (int n = 0; n < 8; n++)
#pragma unroll
            for (int i = 0; i < 4; i++) acc[m][n][i] = 0.0f;

    const int gr = tid >> 3;          // 0..31
    const int gc = (tid & 7) * 4;     // 0..28

    float4 ra[4], rb[4];
    auto ldg = [&](int k0) {
#pragma unroll
        for (int it = 0; it < 4; it++) {
            int row = it * 32 + gr;
            ra[it] = *reinterpret_cast<const float4*>(
                A + (size_t)(bm + row) * 1024 + k0 + gc);
            rb[it] = *reinterpret_cast<const float4*>(
                W + (size_t)(bn + row) * 1024 + k0 + gc);
        }
    };

    auto cvt4 = [](float4 v) {
        return make_float4(__uint_as_float(f2tf32(v.x)),
                           __uint_as_float(f2tf32(v.y)),
                           __uint_as_float(f2tf32(v.z)),
                           __uint_as_float(f2tf32(v.w)));
    };

    auto sts = [&](float* sA, float* sB) {
#pragma unroll
        for (int it = 0; it < 4; it++) {
            int row = it * 32 + gr;
            *reinterpret_cast<float4*>(sA + row * GP + gc) = cvt4(ra[it]);
            *reinterpret_cast<float4*>(sB + row * GP + gc) = cvt4(rb[it]);
        }
    };

    auto compute = [&](const float* sA, const float* sB) {
#pragma unroll
        for (int ks = 0; ks < 4; ks++) {
            uint32_t af[2][4];
#pragma unroll
            for (int m = 0; m < 2; m++) {
                const float* ap = sA + (wm * 32 + m * 16 + r) * GP + ks * 8 + c;
                af[m][0] = __float_as_uint(ap[0]);
                af[m][1] = __float_as_uint(ap[8 * GP]);
                af[m][2] = __float_as_uint(ap[4]);
                af[m][3] = __float_as_uint(ap[8 * GP + 4]);
            }
            uint32_t bf[8][2];
#pragma unroll
            for (int n = 0; n < 8; n++) {
                const float* bp = sB + (wn * 64 + n * 8 + r) * GP + ks * 8 + c;
                bf[n][0] = __float_as_uint(bp[0]);
                bf[n][1] = __float_as_uint(bp[4]);
            }
#pragma unroll
            for (int m = 0; m < 2; m++)
#pragma unroll
                for (int n = 0; n < 8; n++) mma_tf32(acc[m][n], af[m], bf[n]);
        }
    };

    float* buf0 = sm;                     // [A | B] stage 0
    float* buf1 = sm + 2 * GSTAGE;        // [A | B] stage 1

    ldg(0);
    sts(buf0, buf0 + GSTAGE);
    __syncthreads();

    for (int t = 0; t < 32; t++) {
        float* cur = (t & 1) ? buf1 : buf0;
        float* nxt = (t & 1) ? buf0 : buf1;
        if (t < 31) ldg((t + 1) * 32);
        compute(cur, cur + GSTAGE);
        if (t < 31) {
            sts(nxt, nxt + GSTAGE);
            __syncthreads();
        }
    }

    const int qr = lane >> 2;
    const int qc = (lane & 3) * 2;
#pragma unroll
    for (int m = 0; m < 2; m++) {
        const int row0 = bm + wm * 32 + m * 16 + qr;
#pragma unroll
        for (int n = 0; n < 8; n++) {
            const int col = bn + wn * 64 + n * 8 + qc;
            *reinterpret_cast<float2*>(C + (size_t)row0 * 1024 + col) =
                make_float2(acc[m][n][0], acc[m][n][1]);
            *reinterpret_cast<float2*>(C + (size_t)(row0 + 8) * 1024 + col) =
                make_float2(acc[m][n][2], acc[m][n][3]);
        }
    }
}

// ============ tf32 tensor-core flash attention (unchanged) ================
#define KVPITCH 68
#define ATTN_SMEM (2 * 64 * KVPITCH * 4)   // 34816 B

__global__ void __launch_bounds__(256, 1)
attn_tc_kernel(const float* __restrict__ Q, const float* __restrict__ K,
               const float* __restrict__ V, float* __restrict__ O) {
    extern __shared__ float sm[];
    float* Ks = sm;                  // 64 x 68
    float* Vs = sm + 64 * KVPITCH;   // 64 x 68

    const int tid = threadIdx.x;
    const int lane = tid & 31;
    const int wid = tid >> 5;
    const int c = lane & 3;
    const int r = lane >> 2;
    const int b = blockIdx.z;
    const int h = blockIdx.y;
    const int q0 = blockIdx.x * 128;
    const int wrow = wid * 16;

    const float* Qb = Q + ((size_t)(b * S + q0) * D) + h * HD;
    const float* Kb = K + ((size_t)b * S) * D + h * HD;
    const float* Vb = V + ((size_t)b * S) * D + h * HD;

    uint32_t qf[8][4];
#pragma unroll
    for (int ks = 0; ks < 8; ks++) {
        const int row0 = wrow + r, row1 = row0 + 8, col = ks * 8 + c;
        qf[ks][0] = f2tf32(Qb[(size_t)row0 * D + col] * 0.125f);
        qf[ks][1] = f2tf32(Qb[(size_t)row1 * D + col] * 0.125f);
        qf[ks][2] = f2tf32(Qb[(size_t)row0 * D + col + 4] * 0.125f);
        qf[ks][3] = f2tf32(Qb[(size_t)row1 * D + col + 4] * 0.125f);
    }

    float oacc[8][4];
#pragma unroll
    for (int n = 0; n < 8; n++)
#pragma unroll
        for (int i = 0; i < 4; i++) oacc[n][i] = 0.0f;
    float m0 = -1e30f, m1 = -1e30f, l0 = 0.0f, l1 = 0.0f;

    for (int kt0 = 0; kt0 < S; kt0 += 64) {
        __syncthreads();
#pragma unroll
        for (int i = 0; i < 4; i++) {
            const int idx = tid + i * 256;
            const int row = idx >> 4, c4 = (idx & 15) * 4;
            float4 kv = *reinterpret_cast<const float4*>(
                Kb + (size_t)(kt0 + row) * D + c4);
            float4 vv = *reinterpret_cast<const float4*>(
                Vb + (size_t)(kt0 + row) * D + c4);
            float4 kc = make_float4(__uint_as_float(f2tf32(kv.x)),
                                    __uint_as_float(f2tf32(kv.y)),
                                    __uint_as_float(f2tf32(kv.z)),
                                    __uint_as_float(f2tf32(kv.w)));
            float4 vc = make_float4(__uint_as_float(f2tf32(vv.x)),
                                    __uint_as_float(f2tf32(vv.y)),
                                    __uint_as_float(f2tf32(vv.z)),
                                    __uint_as_float(f2tf32(vv.w)));
            *reinterpret_cast<float4*>(Ks + row * KVPITCH + c4) = kc;
            *reinterpret_cast<float4*>(Vs + row * KVPITCH + c4) = vc;
        }
        __syncthreads();

        float sacc[8][4];
#pragma unroll
        for (int n = 0; n < 8; n++)
#pragma unroll
            for (int i = 0; i < 4; i++) sacc[n][i] = 0.0f;

#pragma unroll
        for (int ks = 0; ks < 8; ks++) {
#pragma unroll
            for (int nt = 0; nt < 8; nt++) {
                uint32_t bf[2];
                const float* kp = Ks + (nt * 8 + r) * KVPITCH + ks * 8 + c;
                bf[0] = __float_as_uint(kp[0]);
                bf[1] = __float_as_uint(kp[4]);
                mma_tf32(sacc[nt], qf[ks], bf);
            }
        }

        float rmax0 = -1e30f, rmax1 = -1e30f;
#pragma unroll
        for (int nt = 0; nt < 8; nt++) {
            rmax0 = fmaxf(rmax0, fmaxf(sacc[nt][0], sacc[nt][1]));
            rmax1 = fmaxf(rmax1, fmaxf(sacc[nt][2], sacc[nt][3]));
        }
#pragma unroll
        for (int off = 1; off <= 2; off <<= 1) {
            rmax0 = fmaxf(rmax0, __shfl_xor_sync(0xffffffffu, rmax0, off));
            rmax1 = fmaxf(rmax1, __shfl_xor_sync(0xffffffffu, rmax1, off));
        }
        const float mn0 = fmaxf(m0, rmax0);
        const float mn1 = fmaxf(m1, rmax1);
        const float alpha0 = __expf(m0 - mn0);
        const float alpha1 = __expf(m1 - mn1);
        float rs0 = 0.0f, rs1 = 0.0f;
#pragma unroll
        for (int nt = 0; nt < 8; nt++) {
            sacc[nt][0] = __expf(sacc[nt][0] - mn0);
            sacc[nt][1] = __expf(sacc[nt][1] - mn0);
            sacc[nt][2] = __expf(sacc[nt][2] - mn1);
            sacc[nt][3] = __expf(sacc[nt][3] - mn1);
            rs0 += sacc[nt][0] + sacc[nt][1];
            rs1 += sacc[nt][2] + sacc[nt][3];
        }
#pragma unroll
        for (int off = 1; off <= 2; off <<= 1) {
            rs0 += __shfl_xor_sync(0xffffffffu, rs0, off);
            rs1 += __shfl_xor_sync(0xffffffffu, rs1, off);
        }
        l0 = l0 * alpha0 + rs0;
        l1 = l1 * alpha1 + rs1;
        m0 = mn0;
        m1 = mn1;
#pragma unroll
        for (int nt = 0; nt < 8; nt++) {
            oacc[nt][0] *= alpha0;
            oacc[nt][1] *= alpha0;
            oacc[nt][2] *= alpha1;
            oacc[nt][3] *= alpha1;
        }

        const int srcA = (lane & ~3) | (c >> 1);
        const int srcB = srcA + 2;
#pragma unroll
        for (int kt = 0; kt < 8; kt++) {
            const float v00 = __shfl_sync(0xffffffffu, sacc[kt][0], srcA);
            const float v01 = __shfl_sync(0xffffffffu, sacc[kt][1], srcA);
            const float v20 = __shfl_sync(0xffffffffu, sacc[kt][2], srcA);
            const float v21 = __shfl_sync(0xffffffffu, sacc[kt][3], srcA);
            const float w00 = __shfl_sync(0xffffffffu, sacc[kt][0], srcB);
            const float w01 = __shfl_sync(0xffffffffu, sacc[kt][1], srcB);
            const float w20 = __shfl_sync(0xffffffffu, sacc[kt][2], srcB);
            const float w21 = __shfl_sync(0xffffffffu, sacc[kt][3], srcB);
            uint32_t af[4];
            af[0] = f2tf32((c & 1) ? v01 : v00);
            af[1] = f2tf32((c & 1) ? v21 : v20);
            af[2] = f2tf32((c & 1) ? w01 : w00);
            af[3] = f2tf32((c & 1) ? w21 : w20);
#pragma unroll
            for (int nt = 0; nt < 8; nt++) {
                uint32_t bf[2];
                const float* vp = Vs + (kt * 8 + c) * KVPITCH + nt * 8 + r;
                bf[0] = __float_as_uint(vp[0]);
                bf[1] = __float_as_uint(vp[4 * KVPITCH]);
                mma_tf32(oacc[nt], af, bf);
            }
        }
    }

    const float inv0 = 1.0f / l0;
    const float inv1 = 1.0f / l1;
    float* Ob = O + ((size_t)(b * S + q0 + wrow) * D) + h * HD;
#pragma unroll
    for (int nt = 0; nt < 8; nt++) {
        const int col = nt * 8 + 2 * c;
        *reinterpret_cast<float2*>(Ob + (size_t)r * D + col) =
            make_float2(oacc[nt][0] * inv0, oacc[nt][1] * inv0);
        *reinterpret_cast<float2*>(Ob + (size_t)(r + 8) * D + col) =
            make_float2(oacc[nt][2] * inv1, oacc[nt][3] * inv1);
    }
}

// ---------------- launch ----------------
extern "C" void kernel_launch(void* const* d_in, const int* in_sizes, int n_in,
                              void* d_out, int out_size) {
    const float* x  = (const float*)d_in[0];
    const float* wq = (const float*)d_in[1];
    const float* wk = (const float*)d_in[2];
    const float* wv = (const float*)d_in[3];
    const float* wo = (const float*)d_in[4];
    float* out = (float*)d_out;

    float* q;  cudaGetSymbolAddress((void**)&q,  g_q);
    float* k;  cudaGetSymbolAddress((void**)&k,  g_k);
    float* v;  cudaGetSymbolAddress((void**)&v,  g_v);
    float* ao; cudaGetSymbolAddress((void**)&ao, g_ao);

    cudaFuncSetAttribute(gemm_tc_kernel,
                         cudaFuncAttributeMaxDynamicSharedMemorySize, GEMM_SMEM);
    cudaFuncSetAttribute(attn_tc_kernel,
                         cudaFuncAttributeMaxDynamicSharedMemorySize, ATTN_SMEM);

    dim3 gemm_grid(D / 128, MROWS / 128);   // (8, 64)
    gemm_tc_kernel<<<gemm_grid, 256, GEMM_SMEM>>>(x, wq, q);
    gemm_tc_kernel<<<gemm_grid, 256, GEMM_SMEM>>>(x, wk, k);
    gemm_tc_kernel<<<gemm_grid, 256, GEMM_SMEM>>>(x, wv, v);

    dim3 attn_grid(S / 128, H, B);          // (8, 16, 8)
    attn_tc_kernel<<<attn_grid, 256, ATTN_SMEM>>>(q, k, v, ao);

    gemm_tc_kernel<<<gemm_grid, 256, GEMM_SMEM>>>(ao, wo, out);
}

// round 6
// speedup vs baseline: 5.0084x; 1.0774x over previous
#include <cuda_runtime.h>
#include <math.h>
#include <stdint.h>

// Problem constants
#define B 8
#define S 1024
#define D 1024
#define H 16
#define HD 64
#define MROWS (B * S)   // 8192

// ---------------- scratch (no runtime allocation allowed) ----------------
__device__ float g_q[MROWS * D];
__device__ float g_k[MROWS * D];
__device__ float g_v[MROWS * D];
__device__ float g_ao[MROWS * D];
__device__ float g_x[MROWS * D];        // tf32-rounded x
__device__ float g_wq[D * D];           // tf32-rounded weights
__device__ float g_wk[D * D];
__device__ float g_wv[D * D];
__device__ float g_wo[D * D];

// ===================== tf32 mma helpers ===================================
__device__ __forceinline__ uint32_t f2tf32(float v) {
    uint32_t u;
    asm("cvt.rna.tf32.f32 %0, %1;" : "=r"(u) : "f"(v));
    return u;
}

__device__ __forceinline__ void mma_tf32(float* c, const uint32_t* a,
                                         const uint32_t* b) {
    asm volatile(
        "mma.sync.aligned.m16n8k8.row.col.f32.tf32.tf32.f32 "
        "{%0,%1,%2,%3}, {%4,%5,%6,%7}, {%8,%9}, {%0,%1,%2,%3};"
        : "+f"(c[0]), "+f"(c[1]), "+f"(c[2]), "+f"(c[3])
        : "r"(a[0]), "r"(a[1]), "r"(a[2]), "r"(a[3]), "r"(b[0]), "r"(b[1]));
}

__device__ __forceinline__ uint32_t smem_u32(const void* p) {
    uint32_t a;
    asm("{ .reg .u64 t; cvta.to.shared.u64 t, %1; cvt.u32.u64 %0, t; }"
        : "=r"(a) : "l"(p));
    return a;
}

__device__ __forceinline__ void cp_async16(uint32_t dst, const void* src) {
    asm volatile("cp.async.cg.shared.global [%0], [%1], 16;"
                 :: "r"(dst), "l"(src));
}
#define CP_COMMIT() asm volatile("cp.async.commit_group;" ::: "memory")
#define CP_WAIT(n)  asm volatile("cp.async.wait_group %0;" :: "n"(n) : "memory")

// ================ prep: round arrays to tf32 in gmem ======================
__global__ void round_tf32_kernel(const float* __restrict__ src,
                                  float* __restrict__ dst, int n4) {
    int i = blockIdx.x * blockDim.x + threadIdx.x;
    if (i < n4) {
        float4 v = reinterpret_cast<const float4*>(src)[i];
        reinterpret_cast<float4*>(dst)[i] =
            make_float4(__uint_as_float(f2tf32(v.x)),
                        __uint_as_float(f2tf32(v.y)),
                        __uint_as_float(f2tf32(v.z)),
                        __uint_as_float(f2tf32(v.w)));
    }
}

// ===================== tf32 mma.sync GEMM: C = A * W^T ====================
// Inputs pre-rounded to tf32 -> pure cp.async staging, natural layout
// pitch 36 (bank = 4r+c: conflict-free scalar fragment LDS).
#define GP 36
#define GSTAGE (128 * GP)                // 4608 floats per matrix per stage
#define GEMM_SMEM (2 * 2 * GSTAGE * 4)   // 73728 B

template <bool ROUND_OUT>
__global__ void __launch_bounds__(256, 2)
gemm_tc_kernel(const float* __restrict__ A, const float* __restrict__ W,
               float* __restrict__ C) {
    extern __shared__ float sm[];
    const int tid = threadIdx.x;
    const int lane = tid & 31;
    const int wid = tid >> 5;
    const int wm = wid & 3;
    const int wn = wid >> 2;
    const int c = lane & 3;
    const int r = lane >> 2;
    const int bn = blockIdx.x * 128;
    const int bm = blockIdx.y * 128;

    float acc[2][8][4];
#pragma unroll
    for (int m = 0; m < 2; m++)
#pragma unroll
        for (int n = 0; n < 8; n++)
#pragma unroll
            for (int i = 0; i < 4; i++) acc[m][n][i] = 0.0f;

    const int gr = tid >> 3;          // 0..31
    const int gc = (tid & 7) * 4;     // 0..28

    auto stage = [&](int k0, float* sA, float* sB) {
#pragma unroll
        for (int it = 0; it < 4; it++) {
            int row = it * 32 + gr;
            cp_async16(smem_u32(sA + row * GP + gc),
                       A + (size_t)(bm + row) * 1024 + k0 + gc);
            cp_async16(smem_u32(sB + row * GP + gc),
                       W + (size_t)(bn + row) * 1024 + k0 + gc);
        }
        CP_COMMIT();
    };

    auto compute = [&](const float* sA, const float* sB) {
#pragma unroll
        for (int ks = 0; ks < 4; ks++) {
            uint32_t af[2][4];
#pragma unroll
            for (int m = 0; m < 2; m++) {
                const float* ap = sA + (wm * 32 + m * 16 + r) * GP + ks * 8 + c;
                af[m][0] = __float_as_uint(ap[0]);
                af[m][1] = __float_as_uint(ap[8 * GP]);
                af[m][2] = __float_as_uint(ap[4]);
                af[m][3] = __float_as_uint(ap[8 * GP + 4]);
            }
            uint32_t bf[8][2];
#pragma unroll
            for (int n = 0; n < 8; n++) {
                const float* bp = sB + (wn * 64 + n * 8 + r) * GP + ks * 8 + c;
                bf[n][0] = __float_as_uint(bp[0]);
                bf[n][1] = __float_as_uint(bp[4]);
            }
#pragma unroll
            for (int m = 0; m < 2; m++)
#pragma unroll
                for (int n = 0; n < 8; n++) mma_tf32(acc[m][n], af[m], bf[n]);
        }
    };

    float* buf0 = sm;                     // [A | B] stage 0
    float* buf1 = sm + 2 * GSTAGE;        // [A | B] stage 1

    stage(0, buf0, buf0 + GSTAGE);

    for (int t = 0; t < 32; t++) {
        float* cur = (t & 1) ? buf1 : buf0;
        float* nxt = (t & 1) ? buf0 : buf1;
        __syncthreads();   // all warps done computing on nxt (iter t-1)
        if (t < 31) {
            stage((t + 1) * 32, nxt, nxt + GSTAGE);
            CP_WAIT(1);    // group for cur complete
        } else {
            CP_WAIT(0);
        }
        __syncthreads();   // cur visible to all warps
        compute(cur, cur + GSTAGE);
    }

    const int qr = lane >> 2;
    const int qc = (lane & 3) * 2;
#pragma unroll
    for (int m = 0; m < 2; m++) {
        const int row0 = bm + wm * 32 + m * 16 + qr;
#pragma unroll
        for (int n = 0; n < 8; n++) {
            const int col = bn + wn * 64 + n * 8 + qc;
            float o0 = acc[m][n][0], o1 = acc[m][n][1];
            float o2 = acc[m][n][2], o3 = acc[m][n][3];
            if (ROUND_OUT) {
                o0 = __uint_as_float(f2tf32(o0));
                o1 = __uint_as_float(f2tf32(o1));
                o2 = __uint_as_float(f2tf32(o2));
                o3 = __uint_as_float(f2tf32(o3));
            }
            *reinterpret_cast<float2*>(C + (size_t)row0 * 1024 + col) =
                make_float2(o0, o1);
            *reinterpret_cast<float2*>(C + (size_t)(row0 + 8) * 1024 + col) =
                make_float2(o2, o3);
        }
    }
}

// ============ tf32 tensor-core flash attention (cp.async 2-stage) =========
// Q/K/V pre-rounded to tf32 by GEMM epilogue. KV tiles stream via cp.async.
#define KVPITCH 68
#define SSTAGE (2 * 64 * KVPITCH)          // floats per stage (K+V)
#define ATTN_SMEM (2 * SSTAGE * 4)         // 69632 B

__global__ void __launch_bounds__(256, 1)
attn_tc_kernel(const float* __restrict__ Q, const float* __restrict__ K,
               const float* __restrict__ V, float* __restrict__ O) {
    extern __shared__ float sm[];

    const int tid = threadIdx.x;
    const int lane = tid & 31;
    const int wid = tid >> 5;
    const int c = lane & 3;
    const int r = lane >> 2;
    const int b = blockIdx.z;
    const int h = blockIdx.y;
    const int q0 = blockIdx.x * 128;
    const int wrow = wid * 16;

    const float* Qb = Q + ((size_t)(b * S + q0) * D) + h * HD;
    const float* Kb = K + ((size_t)b * S) * D + h * HD;
    const float* Vb = V + ((size_t)b * S) * D + h * HD;

    auto load_kv = [&](int kt0, float* base) {
        float* Kst = base;
        float* Vst = base + 64 * KVPITCH;
#pragma unroll
        for (int i = 0; i < 4; i++) {
            const int idx = tid + i * 256;
            const int row = idx >> 4, c4 = (idx & 15) * 4;
            cp_async16(smem_u32(Kst + row * KVPITCH + c4),
                       Kb + (size_t)(kt0 + row) * D + c4);
            cp_async16(smem_u32(Vst + row * KVPITCH + c4),
                       Vb + (size_t)(kt0 + row) * D + c4);
        }
        CP_COMMIT();
    };

    // Q fragments (values already tf32; *0.125 is exact)
    uint32_t qf[8][4];
#pragma unroll
    for (int ks = 0; ks < 8; ks++) {
        const int row0 = wrow + r, row1 = row0 + 8, col = ks * 8 + c;
        qf[ks][0] = __float_as_uint(Qb[(size_t)row0 * D + col] * 0.125f);
        qf[ks][1] = __float_as_uint(Qb[(size_t)row1 * D + col] * 0.125f);
        qf[ks][2] = __float_as_uint(Qb[(size_t)row0 * D + col + 4] * 0.125f);
        qf[ks][3] = __float_as_uint(Qb[(size_t)row1 * D + col + 4] * 0.125f);
    }

    float oacc[8][4];
#pragma unroll
    for (int n = 0; n < 8; n++)
#pragma unroll
        for (int i = 0; i < 4; i++) oacc[n][i] = 0.0f;
    float m0 = -1e30f, m1 = -1e30f, l0 = 0.0f, l1 = 0.0f;

    load_kv(0, sm);

    for (int t = 0; t < 16; t++) {
        float* cur = sm + (t & 1) * SSTAGE;
        float* nxt = sm + ((t + 1) & 1) * SSTAGE;
        __syncthreads();   // all warps done with nxt (used at t-1)
        if (t < 15) {
            load_kv((t + 1) * 64, nxt);
            CP_WAIT(1);
        } else {
            CP_WAIT(0);
        }
        __syncthreads();   // cur visible
        const float* Ks = cur;
        const float* Vs = cur + 64 * KVPITCH;

        // S = Q . K^T
        float sacc[8][4];
#pragma unroll
        for (int n = 0; n < 8; n++)
#pragma unroll
            for (int i = 0; i < 4; i++) sacc[n][i] = 0.0f;

#pragma unroll
        for (int ks = 0; ks < 8; ks++) {
#pragma unroll
            for (int nt = 0; nt < 8; nt++) {
                uint32_t bf[2];
                const float* kp = Ks + (nt * 8 + r) * KVPITCH + ks * 8 + c;
                bf[0] = __float_as_uint(kp[0]);
                bf[1] = __float_as_uint(kp[4]);
                mma_tf32(sacc[nt], qf[ks], bf);
            }
        }

        // online softmax on C-fragments
        float rmax0 = -1e30f, rmax1 = -1e30f;
#pragma unroll
        for (int nt = 0; nt < 8; nt++) {
            rmax0 = fmaxf(rmax0, fmaxf(sacc[nt][0], sacc[nt][1]));
            rmax1 = fmaxf(rmax1, fmaxf(sacc[nt][2], sacc[nt][3]));
        }
#pragma unroll
        for (int off = 1; off <= 2; off <<= 1) {
            rmax0 = fmaxf(rmax0, __shfl_xor_sync(0xffffffffu, rmax0, off));
            rmax1 = fmaxf(rmax1, __shfl_xor_sync(0xffffffffu, rmax1, off));
        }
        const float mn0 = fmaxf(m0, rmax0);
        const float mn1 = fmaxf(m1, rmax1);
        const float alpha0 = __expf(m0 - mn0);
        const float alpha1 = __expf(m1 - mn1);
        float rs0 = 0.0f, rs1 = 0.0f;
#pragma unroll
        for (int nt = 0; nt < 8; nt++) {
            sacc[nt][0] = __expf(sacc[nt][0] - mn0);
            sacc[nt][1] = __expf(sacc[nt][1] - mn0);
            sacc[nt][2] = __expf(sacc[nt][2] - mn1);
            sacc[nt][3] = __expf(sacc[nt][3] - mn1);
            rs0 += sacc[nt][0] + sacc[nt][1];
            rs1 += sacc[nt][2] + sacc[nt][3];
        }
#pragma unroll
        for (int off = 1; off <= 2; off <<= 1) {
            rs0 += __shfl_xor_sync(0xffffffffu, rs0, off);
            rs1 += __shfl_xor_sync(0xffffffffu, rs1, off);
        }
        l0 = l0 * alpha0 + rs0;
        l1 = l1 * alpha1 + rs1;
        m0 = mn0;
        m1 = mn1;
#pragma unroll
        for (int nt = 0; nt < 8; nt++) {
            oacc[nt][0] *= alpha0;
            oacc[nt][1] *= alpha0;
            oacc[nt][2] *= alpha1;
            oacc[nt][3] *= alpha1;
        }

        // P (C-frag) -> A-frag via intra-quad shuffles, then O += P.V
        const int srcA = (lane & ~3) | (c >> 1);
        const int srcB = srcA + 2;
#pragma unroll
        for (int kt = 0; kt < 8; kt++) {
            const float v00 = __shfl_sync(0xffffffffu, sacc[kt][0], srcA);
            const float v01 = __shfl_sync(0xffffffffu, sacc[kt][1], srcA);
            const float v20 = __shfl_sync(0xffffffffu, sacc[kt][2], srcA);
            const float v21 = __shfl_sync(0xffffffffu, sacc[kt][3], srcA);
            const float w00 = __shfl_sync(0xffffffffu, sacc[kt][0], srcB);
            const float w01 = __shfl_sync(0xffffffffu, sacc[kt][1], srcB);
            const float w20 = __shfl_sync(0xffffffffu, sacc[kt][2], srcB);
            const float w21 = __shfl_sync(0xffffffffu, sacc[kt][3], srcB);
            uint32_t af[4];
            af[0] = f2tf32((c & 1) ? v01 : v00);
            af[1] = f2tf32((c & 1) ? v21 : v20);
            af[2] = f2tf32((c & 1) ? w01 : w00);
            af[3] = f2tf32((c & 1) ? w21 : w20);
#pragma unroll
            for (int nt = 0; nt < 8; nt++) {
                uint32_t bf[2];
                const float* vp = Vs + (kt * 8 + c) * KVPITCH + nt * 8 + r;
                bf[0] = __float_as_uint(vp[0]);
                bf[1] = __float_as_uint(vp[4 * KVPITCH]);
                mma_tf32(oacc[nt], af, bf);
            }
        }
    }

    // epilogue: divide by l, round to tf32 (consumed by final GEMM), store
    const float inv0 = 1.0f / l0;
    const float inv1 = 1.0f / l1;
    float* Ob = O + ((size_t)(b * S + q0 + wrow) * D) + h * HD;
#pragma unroll
    for (int nt = 0; nt < 8; nt++) {
        const int col = nt * 8 + 2 * c;
        *reinterpret_cast<float2*>(Ob + (size_t)r * D + col) =
            make_float2(__uint_as_float(f2tf32(oacc[nt][0] * inv0)),
                        __uint_as_float(f2tf32(oacc[nt][1] * inv0)));
        *reinterpret_cast<float2*>(Ob + (size_t)(r + 8) * D + col) =
            make_float2(__uint_as_float(f2tf32(oacc[nt][2] * inv1)),
                        __uint_as_float(f2tf32(oacc[nt][3] * inv1)));
    }
}

// ---------------- launch ----------------
extern "C" void kernel_launch(void* const* d_in, const int* in_sizes, int n_in,
                              void* d_out, int out_size) {
    const float* x  = (const float*)d_in[0];
    const float* wq = (const float*)d_in[1];
    const float* wk = (const float*)d_in[2];
    const float* wv = (const float*)d_in[3];
    const float* wo = (const float*)d_in[4];
    float* out = (float*)d_out;

    float* q;   cudaGetSymbolAddress((void**)&q,   g_q);
    float* k;   cudaGetSymbolAddress((void**)&k,   g_k);
    float* v;   cudaGetSymbolAddress((void**)&v,   g_v);
    float* ao;  cudaGetSymbolAddress((void**)&ao,  g_ao);
    float* xr;  cudaGetSymbolAddress((void**)&xr,  g_x);
    float* wqr; cudaGetSymbolAddress((void**)&wqr, g_wq);
    float* wkr; cudaGetSymbolAddress((void**)&wkr, g_wk);
    float* wvr; cudaGetSymbolAddress((void**)&wvr, g_wv);
    float* wor; cudaGetSymbolAddress((void**)&wor, g_wo);

    cudaFuncSetAttribute(gemm_tc_kernel<true>,
                         cudaFuncAttributeMaxDynamicSharedMemorySize, GEMM_SMEM);
    cudaFuncSetAttribute(gemm_tc_kernel<false>,
                         cudaFuncAttributeMaxDynamicSharedMemorySize, GEMM_SMEM);
    cudaFuncSetAttribute(attn_tc_kernel,
                         cudaFuncAttributeMaxDynamicSharedMemorySize, ATTN_SMEM);

    // prep: round x + weights to tf32 once
    const int nx4 = MROWS * D / 4;         // 2097152
    const int nw4 = D * D / 4;             // 262144
    round_tf32_kernel<<<(nx4 + 255) / 256, 256>>>(x, xr, nx4);
    round_tf32_kernel<<<(nw4 + 255) / 256, 256>>>(wq, wqr, nw4);
    round_tf32_kernel<<<(nw4 + 255) / 256, 256>>>(wk, wkr, nw4);
    round_tf32_kernel<<<(nw4 + 255) / 256, 256>>>(wv, wvr, nw4);
    round_tf32_kernel<<<(nw4 + 255) / 256, 256>>>(wo, wor, nw4);

    dim3 gemm_grid(D / 128, MROWS / 128);   // (8, 64)
    gemm_tc_kernel<true><<<gemm_grid, 256, GEMM_SMEM>>>(xr, wqr, q);
    gemm_tc_kernel<true><<<gemm_grid, 256, GEMM_SMEM>>>(xr, wkr, k);
    gemm_tc_kernel<true><<<gemm_grid, 256, GEMM_SMEM>>>(xr, wvr, v);

    dim3 attn_grid(S / 128, H, B);          // (8, 16, 8)
    attn_tc_kernel<<<attn_grid, 256, ATTN_SMEM>>>(q, k, v, ao);

    gemm_tc_kernel<false><<<gemm_grid, 256, GEMM_SMEM>>>(ao, wor, out);
}